// round 3
// baseline (speedup 1.0000x reference)
#include <cuda_runtime.h>
#include <cuda_fp16.h>
#include <cstdint>

// ============================================================================
// FastTSAGEConv fused kernel for GB300, constrained to non-"a" PTX (sm_103):
// legacy HMMA mma.sync.m16n8k16 fp16 (fp32 accum), 1-pass.
//
//   hn[e]  = (sum_{j=ss..me} src_feat[j]) / (deg[e]+1),  ss = me - deg + 1
//   out[e] = [dst_feat[e] | hn[e]] @ [W_self; W_neigh] + (b_self + b_neigh)
//
// A = [dst | hn] (E x 256) built on the fly in smem (fp16), B = W cat
// (256 x 128) pre-packed into per-lane MMA fragment layout by a prep kernel.
// dst_max_eid dtype (int32 vs int64) is auto-detected by a tiny probe kernel.
// ============================================================================

#define TILE_M     128
#define NTHREADS   256

// ---- smem layout ----
static constexpr int SMEM_BFRAG = 0;            // 16*16*32*8 = 65536 B
static constexpr int A_STRIDE_B = 528;          // bytes per A row (256 fp16 + 8 pad)
static constexpr int SMEM_A     = 65536;        // A fp16 [128][528B]  (67.6 KB)
static constexpr int STG_STRIDE = 136;          // floats per out-stage row (pad 8)
// out stage fp32 [128][136] aliases the A region (69632 B)
static constexpr int SMEM_TOTAL = 65536 + TILE_M * STG_STRIDE * 4;   // 135168

// Pre-packed B fragments: [kstep 0..15][nblock 0..15][lane 0..31] x 2 u32
__device__ uint2 g_bfrag[16 * 16 * 32];
// dtype flag for dst_max_eid: 1 if int64, 0 if int32
__device__ int g_eid_is64;

// ============================ helpers ===================================
__device__ __forceinline__ uint32_t smem_to_u32(const void* smem_ptr) {
    uint32_t addr;
    asm("{ .reg .u64 tmp; cvta.to.shared.u64 tmp, %1; cvt.u32.u64 %0, tmp; }"
        : "=r"(addr) : "l"(smem_ptr));
    return addr;
}

__device__ __forceinline__ uint32_t f22u(float a, float b) {
    // half2 with low = a, high = b
    __half2 h = __floats2half2_rn(a, b);
    return *reinterpret_cast<uint32_t*>(&h);
}

__device__ __forceinline__ void mma16816(float* c, const uint32_t* a,
                                         uint32_t b0, uint32_t b1) {
    asm volatile(
        "mma.sync.aligned.m16n8k16.row.col.f32.f16.f16.f32 "
        "{%0,%1,%2,%3}, {%4,%5,%6,%7}, {%8,%9}, {%0,%1,%2,%3};\n"
        : "+f"(c[0]), "+f"(c[1]), "+f"(c[2]), "+f"(c[3])
        : "r"(a[0]), "r"(a[1]), "r"(a[2]), "r"(a[3]), "r"(b0), "r"(b1));
}

// ============================================================================
// Probe kernel: detect whether dst_max_eid is int64.
// Interpreted as int64, elements [E/4, E/4+256) have word indices < E, so the
// reads are in-bounds under either dtype. True int64 data (values < E < 2^31,
// nonnegative) has ALL high words == 0. If the data is int32, the "high words"
// are actual dst_max_eid values of edges near E/2, which are >= seg_start
// (~E/2) and hence nonzero. all-zero => int64.
// ============================================================================
__global__ void probe_eid_kernel(const unsigned* __restrict__ dme_words, int E) {
    __shared__ int nz;
    if (threadIdx.x == 0) nz = 0;
    __syncthreads();
    int i = E / 4 + threadIdx.x;            // element index (int64 view)
    unsigned hi = dme_words[2 * i + 1];     // word index < E, safe either way
    if (hi != 0u) atomicAdd(&nz, 1);
    __syncthreads();
    if (threadIdx.x == 0) g_eid_is64 = (nz == 0) ? 1 : 0;
}

// ============================================================================
// Prep kernel: pack B = [W_self; W_neigh] (256 x 128, fp32) into fp16 MMA
// fragment layout.  For kstep s (k0=16s), nblock nb (n0=8nb), lane l:
//   kA = 16s + (l%4)*2,  n = 8nb + l/4
//   reg0 = half2( B[kA][n],   B[kA+1][n] )
//   reg1 = half2( B[kA+8][n], B[kA+9][n] )
// ============================================================================
__global__ void prep_w_kernel(const float* __restrict__ Wself,
                              const float* __restrict__ Wneigh) {
    int idx = blockIdx.x * blockDim.x + threadIdx.x;    // 0..8191
    if (idx >= 16 * 16 * 32) return;
    int lane = idx & 31;
    int nb   = (idx >> 5) & 15;
    int s    = idx >> 9;
    int k0 = s * 16 + (lane & 3) * 2;
    int n  = nb * 8 + (lane >> 2);

    auto wc = [&](int k) -> float {
        return (k < 128) ? Wself[k * 128 + n] : Wneigh[(k - 128) * 128 + n];
    };
    uint2 v;
    v.x = f22u(wc(k0),     wc(k0 + 1));
    v.y = f22u(wc(k0 + 8), wc(k0 + 9));
    g_bfrag[idx] = v;
}

// ============================================================================
// Main persistent kernel
// ============================================================================
__global__ void __launch_bounds__(NTHREADS, 1)
fused_tsage_kernel(const float* __restrict__ src_feat,
                   const float* __restrict__ dst_feat,
                   const int*   __restrict__ dst_max_eid,
                   const float* __restrict__ dst_deg,
                   const float* __restrict__ b_self,
                   const float* __restrict__ b_neigh,
                   float* __restrict__ out,
                   int E, int num_tiles) {
    extern __shared__ char smem[];
    const uint32_t smem_base = smem_to_u32(smem);
    const int tid = threadIdx.x;
    const int wid = tid >> 5;
    const int lid = tid & 31;
    const int wm  = wid & 3;        // M-warp 0..3  (rows wm*32 .. +31)
    const int wn  = wid >> 2;       // N-warp 0..1  (cols wn*64 .. +63)
    const int is64 = g_eid_is64;
    const long long* dme64 = reinterpret_cast<const long long*>(dst_max_eid);

    // ---- load pre-packed B fragments into smem (resident all kernel) ----
    {
        const uint4* src4 = reinterpret_cast<const uint4*>(g_bfrag);
        uint4* dst4 = reinterpret_cast<uint4*>(smem + SMEM_BFRAG);
        for (int i = tid; i < 65536 / 16; i += NTHREADS) dst4[i] = src4[i];
    }

    // per-lane bias for the coalesced epilogue (cols 4*lid..4*lid+3)
    const float bia0 = b_self[4 * lid + 0] + b_neigh[4 * lid + 0];
    const float bia1 = b_self[4 * lid + 1] + b_neigh[4 * lid + 1];
    const float bia2 = b_self[4 * lid + 2] + b_neigh[4 * lid + 2];
    const float bia3 = b_self[4 * lid + 3] + b_neigh[4 * lid + 3];

    // ldmatrix per-lane address pieces (A tile, 528B row stride)
    const int ldsm_row = (lid & 7) + ((lid >> 3) & 1) * 8;   // row within 16
    const int ldsm_k16 = (lid >> 4) * 16;                    // +16B for k 8..15
    const uint32_t a_base = smem_base + SMEM_A;

    float* stage = reinterpret_cast<float*>(smem + SMEM_A);  // fp32 view (aliased)

    __syncthreads();

    for (int t = blockIdx.x; t < num_tiles; t += gridDim.x) {
        const int m0 = t * TILE_M;

        // ================= producer phase: build A tile (fp16) ==============
        // dst_feat -> A cols 0..127  (warp-per-edge, fully coalesced)
#pragma unroll 4
        for (int rr = 0; rr < 16; rr++) {
            const int r = wid * 16 + rr;
            const int e = m0 + r;
            if (e < E) {
                float4 v = __ldg(reinterpret_cast<const float4*>(
                    dst_feat + (size_t)e * 128 + 4 * lid));
                uint32_t h01 = f22u(v.x, v.y);
                uint32_t h23 = f22u(v.z, v.w);
                uint32_t addr = a_base + (uint32_t)r * A_STRIDE_B + 8u * lid;
                asm volatile("st.shared.v2.b32 [%0], {%1,%2};"
                             :: "r"(addr), "r"(h01), "r"(h23) : "memory");
            }
        }
        // hn -> A cols 128..255 (segment mean; rows cached in L1/L2 across edges)
#pragma unroll 1
        for (int rr = 0; rr < 16; rr++) {
            const int r = wid * 16 + rr;
            const int e = m0 + r;
            if (e < E) {
                int me = is64 ? (int)dme64[e] : dst_max_eid[e];
                const float degf = dst_deg[e];
                // clamp: stay bounded even under a dtype mis-parse
                if (me >= E) me = E - 1;
                if (me < 0)  me = 0;
                int ss = me - (int)degf + 1;
                if (ss < 0) ss = 0;
                float ax = 0.f, ay = 0.f, az = 0.f, aw = 0.f;
#pragma unroll 2
                for (int j = ss; j <= me; j++) {
                    float4 v = __ldg(reinterpret_cast<const float4*>(
                        src_feat + (size_t)j * 128 + 4 * lid));
                    ax += v.x; ay += v.y; az += v.z; aw += v.w;
                }
                const float inv = 1.0f / (degf + 1.0f);
                uint32_t h01 = f22u(ax * inv, ay * inv);
                uint32_t h23 = f22u(az * inv, aw * inv);
                uint32_t addr = a_base + (uint32_t)r * A_STRIDE_B + 256u + 8u * lid;
                asm volatile("st.shared.v2.b32 [%0], {%1,%2};"
                             :: "r"(addr), "r"(h01), "r"(h23) : "memory");
            }
        }
        __syncthreads();

        // ================= MMA phase: warp tile 32x64, K=256 ================
        float acc[2][8][4];
#pragma unroll
        for (int mi = 0; mi < 2; mi++)
#pragma unroll
            for (int nb = 0; nb < 8; nb++)
#pragma unroll
                for (int q = 0; q < 4; q++) acc[mi][nb][q] = 0.f;

        const uint32_t bfrag_base = smem_base + SMEM_BFRAG;
#pragma unroll 4
        for (int s = 0; s < 16; s++) {
            uint32_t a[2][4];
#pragma unroll
            for (int mi = 0; mi < 2; mi++) {
                const int row0 = wm * 32 + mi * 16;
                uint32_t addr = a_base + (uint32_t)(row0 + ldsm_row) * A_STRIDE_B
                              + (uint32_t)ldsm_k16 + (uint32_t)s * 32u;
                asm volatile(
                    "ldmatrix.sync.aligned.m8n8.x4.shared.b16 {%0,%1,%2,%3}, [%4];"
                    : "=r"(a[mi][0]), "=r"(a[mi][1]), "=r"(a[mi][2]), "=r"(a[mi][3])
                    : "r"(addr));
            }
#pragma unroll
            for (int nb = 0; nb < 8; nb++) {
                uint32_t b0, b1;
                uint32_t baddr = bfrag_base
                    + ((uint32_t)((s * 16 + wn * 8 + nb) * 32 + lid)) * 8u;
                asm volatile("ld.shared.v2.b32 {%0,%1}, [%2];"
                             : "=r"(b0), "=r"(b1) : "r"(baddr));
                mma16816(acc[0][nb], a[0], b0, b1);
                mma16816(acc[1][nb], a[1], b0, b1);
            }
        }
        __syncthreads();   // all warps done reading A before stage overwrite

        // ================= epilogue: regs -> fp32 stage (aliases A) =========
#pragma unroll
        for (int mi = 0; mi < 2; mi++) {
#pragma unroll
            for (int nb = 0; nb < 8; nb++) {
                const int r0 = wm * 32 + mi * 16 + (lid >> 2);
                const int n  = wn * 64 + nb * 8 + (lid & 3) * 2;
                float* p0 = stage + r0 * STG_STRIDE + n;
                p0[0] = acc[mi][nb][0];
                p0[1] = acc[mi][nb][1];
                float* p1 = stage + (r0 + 8) * STG_STRIDE + n;
                p1[0] = acc[mi][nb][2];
                p1[1] = acc[mi][nb][3];
            }
        }
        __syncthreads();

        // ================= coalesced store with bias ========================
#pragma unroll 4
        for (int rr = 0; rr < 16; rr++) {
            const int r = wid * 16 + rr;
            const int e = m0 + r;
            if (e < E) {
                const float* sp = stage + r * STG_STRIDE + 4 * lid;
                float4 v;
                v.x = sp[0] + bia0;
                v.y = sp[1] + bia1;
                v.z = sp[2] + bia2;
                v.w = sp[3] + bia3;
                *reinterpret_cast<float4*>(out + (size_t)e * 128 + 4 * lid) = v;
            }
        }
        __syncthreads();   // stage free before next tile's A writes
    }
}

// ============================================================================
// Launch
// ============================================================================
extern "C" void kernel_launch(void* const* d_in, const int* in_sizes, int n_in,
                              void* d_out, int out_size) {
    const float* src   = (const float*)d_in[0];   // src_feat   [E,128] f32
    const float* dstf  = (const float*)d_in[1];   // dst_feat   [E,128] f32
    // d_in[2] = dst_ids (unused: seg_start = dst_max_eid - deg + 1)
    const int*   dme   = (const int*)  d_in[3];   // dst_max_eid [E] i32 or i64
    const float* deg   = (const float*)d_in[4];   // dst_deg    [E] f32
    const float* Wself = (const float*)d_in[5];   // [128,128] f32
    const float* bself = (const float*)d_in[6];   // [128] f32
    const float* Wnei  = (const float*)d_in[7];   // [128,128] f32
    const float* bnei  = (const float*)d_in[8];   // [128] f32
    float* out = (float*)d_out;

    const int E = in_sizes[4];
    const int num_tiles = (E + TILE_M - 1) / TILE_M;

    probe_eid_kernel<<<1, 256>>>((const unsigned*)dme, E);
    prep_w_kernel<<<(16 * 16 * 32 + 255) / 256, 256>>>(Wself, Wnei);

    int sm_count = 148;
    cudaDeviceGetAttribute(&sm_count, cudaDevAttrMultiProcessorCount, 0);
    const int grid = num_tiles < sm_count ? num_tiles : sm_count;

    cudaFuncSetAttribute(fused_tsage_kernel,
                         cudaFuncAttributeMaxDynamicSharedMemorySize, SMEM_TOTAL);
    fused_tsage_kernel<<<grid, NTHREADS, SMEM_TOTAL>>>(
        src, dstf, dme, deg, bself, bnei, out, E, num_tiles);
}

// round 4
// speedup vs baseline: 1.1685x; 1.1685x over previous
#include <cuda_runtime.h>
#include <cuda_fp16.h>
#include <cstdint>

// ============================================================================
// FastTSAGEConv fused kernel for GB300 (plain sm_103 PTX feature set):
// legacy HMMA mma.sync.m16n8k16 fp16 (fp32 accum), 1-pass.
//
//   hn[e]  = (sum_{j=ss..me} src_feat[j]) / (deg[e]+1),  ss = me - deg + 1
//   out[e] = [dst_feat[e] | hn[e]] @ [W_self; W_neigh] + (b_self + b_neigh)
//
// R3 -> R4: TILE_M 128 -> 64 shrinks smem to ~98KB so 2 CTAs co-reside per SM
// (occupancy 2): one CTA's MMA phase overlaps the other's latency-bound
// staging. dst-load and segment-sum merged into one loop (higher MLP).
// Probe merged into prep kernel (2 launches per replay).
// ============================================================================

#define TILE_M     64
#define NTHREADS   256

// ---- smem layout ----
static constexpr int SMEM_BFRAG = 0;            // 16*16*32*8 = 65536 B
static constexpr int A_STRIDE_B = 528;          // bytes per A row (256 fp16 + 8 pad)
static constexpr int SMEM_A     = 65536;        // A fp16 [64][528B] = 33792 B
static constexpr int STG_STRIDE = 136;          // floats per out-stage row (pad 8)
// out stage fp32 [64][136] aliases the A region (34816 B)
static constexpr int SMEM_TOTAL = 65536 + TILE_M * STG_STRIDE * 4;   // 100352

// Pre-packed B fragments: [kstep 0..15][nblock 0..15][lane 0..31] x 2 u32
__device__ uint2 g_bfrag[16 * 16 * 32];
// dtype flag for dst_max_eid: 1 if int64, 0 if int32
__device__ int g_eid_is64;

// ============================ helpers ===================================
__device__ __forceinline__ uint32_t smem_to_u32(const void* smem_ptr) {
    uint32_t addr;
    asm("{ .reg .u64 tmp; cvta.to.shared.u64 tmp, %1; cvt.u32.u64 %0, tmp; }"
        : "=r"(addr) : "l"(smem_ptr));
    return addr;
}

__device__ __forceinline__ uint32_t f22u(float a, float b) {
    __half2 h = __floats2half2_rn(a, b);
    return *reinterpret_cast<uint32_t*>(&h);
}

__device__ __forceinline__ void mma16816(float* c, const uint32_t* a,
                                         uint32_t b0, uint32_t b1) {
    asm volatile(
        "mma.sync.aligned.m16n8k16.row.col.f32.f16.f16.f32 "
        "{%0,%1,%2,%3}, {%4,%5,%6,%7}, {%8,%9}, {%0,%1,%2,%3};\n"
        : "+f"(c[0]), "+f"(c[1]), "+f"(c[2]), "+f"(c[3])
        : "r"(a[0]), "r"(a[1]), "r"(a[2]), "r"(a[3]), "r"(b0), "r"(b1));
}

// ============================================================================
// Prep kernel (also hosts the dtype probe in block 0):
// pack B = [W_self; W_neigh] (256 x 128 f32) into fp16 MMA fragment layout.
// For kstep s (k0=16s), nblock nb (n0=8nb), lane l:
//   kA = 16s + (l%4)*2,  n = 8nb + l/4
//   reg0 = half2( B[kA][n],   B[kA+1][n] )
//   reg1 = half2( B[kA+8][n], B[kA+9][n] )
// Probe: view dst_max_eid as int64 at elements [E/4, E/4+256) (word indices
// < E under either dtype). True int64 (all values in [0, E)) has all-zero
// high words; int32 data there holds values ~E/2 != 0.
// ============================================================================
__global__ void prep_w_kernel(const float* __restrict__ Wself,
                              const float* __restrict__ Wneigh,
                              const unsigned* __restrict__ dme_words, int E) {
    if (blockIdx.x == 0) {
        __shared__ int nz;
        if (threadIdx.x == 0) nz = 0;
        __syncthreads();
        int i = E / 4 + threadIdx.x;
        unsigned hi = dme_words[2 * i + 1];
        if (hi != 0u) atomicAdd(&nz, 1);
        __syncthreads();
        if (threadIdx.x == 0) g_eid_is64 = (nz == 0) ? 1 : 0;
    }
    int idx = blockIdx.x * blockDim.x + threadIdx.x;    // 0..8191
    if (idx >= 16 * 16 * 32) return;
    int lane = idx & 31;
    int nb   = (idx >> 5) & 15;
    int s    = idx >> 9;
    int k0 = s * 16 + (lane & 3) * 2;
    int n  = nb * 8 + (lane >> 2);

    auto wc = [&](int k) -> float {
        return (k < 128) ? Wself[k * 128 + n] : Wneigh[(k - 128) * 128 + n];
    };
    uint2 v;
    v.x = f22u(wc(k0),     wc(k0 + 1));
    v.y = f22u(wc(k0 + 8), wc(k0 + 9));
    g_bfrag[idx] = v;
}

// ============================================================================
// Main persistent kernel — 2 CTAs/SM
// ============================================================================
__global__ void __launch_bounds__(NTHREADS, 2)
fused_tsage_kernel(const float* __restrict__ src_feat,
                   const float* __restrict__ dst_feat,
                   const int*   __restrict__ dst_max_eid,
                   const float* __restrict__ dst_deg,
                   const float* __restrict__ b_self,
                   const float* __restrict__ b_neigh,
                   float* __restrict__ out,
                   int E, int num_tiles) {
    extern __shared__ char smem[];
    const uint32_t smem_base = smem_to_u32(smem);
    const int tid = threadIdx.x;
    const int wid = tid >> 5;
    const int lid = tid & 31;
    const int wm  = wid & 3;        // M-warp 0..3  (rows wm*16 .. +15)
    const int wn  = wid >> 2;       // N-warp 0..1  (cols wn*64 .. +63)
    const int is64 = g_eid_is64;
    const long long* dme64 = reinterpret_cast<const long long*>(dst_max_eid);

    // ---- load pre-packed B fragments into smem (resident all kernel) ----
    {
        const uint4* src4 = reinterpret_cast<const uint4*>(g_bfrag);
        uint4* dst4 = reinterpret_cast<uint4*>(smem + SMEM_BFRAG);
        for (int i = tid; i < 65536 / 16; i += NTHREADS) dst4[i] = src4[i];
    }

    // per-lane bias for the coalesced epilogue (cols 4*lid..4*lid+3)
    const float bia0 = b_self[4 * lid + 0] + b_neigh[4 * lid + 0];
    const float bia1 = b_self[4 * lid + 1] + b_neigh[4 * lid + 1];
    const float bia2 = b_self[4 * lid + 2] + b_neigh[4 * lid + 2];
    const float bia3 = b_self[4 * lid + 3] + b_neigh[4 * lid + 3];

    // ldmatrix per-lane address pieces (A tile, 528B row stride)
    const int ldsm_row = (lid & 7) + ((lid >> 3) & 1) * 8;   // row within 16
    const int ldsm_k16 = (lid >> 4) * 16;                    // +16B for k 8..15
    const uint32_t a_base = smem_base + SMEM_A;

    float* stage = reinterpret_cast<float*>(smem + SMEM_A);  // fp32 view (aliased)

    __syncthreads();

    for (int t = blockIdx.x; t < num_tiles; t += gridDim.x) {
        const int m0 = t * TILE_M;

        // ========= producer phase: build A tile (fp16), merged loop =========
        // dst_feat -> cols 0..127 ; hn -> cols 128..255 (warp-per-edge)
#pragma unroll 1
        for (int rr = 0; rr < 8; rr++) {
            const int r = wid * 8 + rr;
            const int e = m0 + r;
            if (e < E) {
                // issue dst load first so it overlaps the segsum chain
                float4 dv = __ldg(reinterpret_cast<const float4*>(
                    dst_feat + (size_t)e * 128 + 4 * lid));

                int me = is64 ? (int)dme64[e] : dst_max_eid[e];
                const float degf = dst_deg[e];
                if (me >= E) me = E - 1;           // bounded under any mis-parse
                if (me < 0)  me = 0;
                int ss = me - (int)degf + 1;
                if (ss < 0) ss = 0;
                float ax = 0.f, ay = 0.f, az = 0.f, aw = 0.f;
#pragma unroll 2
                for (int j = ss; j <= me; j++) {
                    float4 v = __ldg(reinterpret_cast<const float4*>(
                        src_feat + (size_t)j * 128 + 4 * lid));
                    ax += v.x; ay += v.y; az += v.z; aw += v.w;
                }
                const float inv = 1.0f / (degf + 1.0f);

                uint32_t addr = a_base + (uint32_t)r * A_STRIDE_B + 8u * lid;
                uint32_t d01 = f22u(dv.x, dv.y);
                uint32_t d23 = f22u(dv.z, dv.w);
                asm volatile("st.shared.v2.b32 [%0], {%1,%2};"
                             :: "r"(addr), "r"(d01), "r"(d23) : "memory");
                uint32_t h01 = f22u(ax * inv, ay * inv);
                uint32_t h23 = f22u(az * inv, aw * inv);
                asm volatile("st.shared.v2.b32 [%0], {%1,%2};"
                             :: "r"(addr + 256u), "r"(h01), "r"(h23) : "memory");
            }
        }
        __syncthreads();

        // ========= MMA phase: warp tile 16x64, K=256 ========================
        float acc[8][4];
#pragma unroll
        for (int nb = 0; nb < 8; nb++)
#pragma unroll
            for (int q = 0; q < 4; q++) acc[nb][q] = 0.f;

        const uint32_t bfrag_base = smem_base + SMEM_BFRAG;
#pragma unroll 4
        for (int s = 0; s < 16; s++) {
            uint32_t a[4];
            {
                const int row0 = wm * 16;
                uint32_t addr = a_base + (uint32_t)(row0 + ldsm_row) * A_STRIDE_B
                              + (uint32_t)ldsm_k16 + (uint32_t)s * 32u;
                asm volatile(
                    "ldmatrix.sync.aligned.m8n8.x4.shared.b16 {%0,%1,%2,%3}, [%4];"
                    : "=r"(a[0]), "=r"(a[1]), "=r"(a[2]), "=r"(a[3])
                    : "r"(addr));
            }
#pragma unroll
            for (int nb = 0; nb < 8; nb++) {
                uint32_t b0, b1;
                uint32_t baddr = bfrag_base
                    + ((uint32_t)((s * 16 + wn * 8 + nb) * 32 + lid)) * 8u;
                asm volatile("ld.shared.v2.b32 {%0,%1}, [%2];"
                             : "=r"(b0), "=r"(b1) : "r"(baddr));
                mma16816(acc[nb], a, b0, b1);
            }
        }
        __syncthreads();   // all warps done reading A before stage overwrite

        // ========= epilogue: regs -> fp32 stage (aliases A) =================
#pragma unroll
        for (int nb = 0; nb < 8; nb++) {
            const int r0 = wm * 16 + (lid >> 2);
            const int n  = wn * 64 + nb * 8 + (lid & 3) * 2;
            float* p0 = stage + r0 * STG_STRIDE + n;
            p0[0] = acc[nb][0];
            p0[1] = acc[nb][1];
            float* p1 = stage + (r0 + 8) * STG_STRIDE + n;
            p1[0] = acc[nb][2];
            p1[1] = acc[nb][3];
        }
        __syncthreads();

        // ========= coalesced store with bias ================================
#pragma unroll 2
        for (int rr = 0; rr < 8; rr++) {
            const int r = wid * 8 + rr;
            const int e = m0 + r;
            if (e < E) {
                const float* sp = stage + r * STG_STRIDE + 4 * lid;
                float4 v;
                v.x = sp[0] + bia0;
                v.y = sp[1] + bia1;
                v.z = sp[2] + bia2;
                v.w = sp[3] + bia3;
                *reinterpret_cast<float4*>(out + (size_t)e * 128 + 4 * lid) = v;
            }
        }
        __syncthreads();   // stage free before next tile's A writes
    }
}

// ============================================================================
// Launch
// ============================================================================
extern "C" void kernel_launch(void* const* d_in, const int* in_sizes, int n_in,
                              void* d_out, int out_size) {
    const float* src   = (const float*)d_in[0];   // src_feat   [E,128] f32
    const float* dstf  = (const float*)d_in[1];   // dst_feat   [E,128] f32
    // d_in[2] = dst_ids (unused: seg_start = dst_max_eid - deg + 1)
    const int*   dme   = (const int*)  d_in[3];   // dst_max_eid [E] i32 or i64
    const float* deg   = (const float*)d_in[4];   // dst_deg    [E] f32
    const float* Wself = (const float*)d_in[5];   // [128,128] f32
    const float* bself = (const float*)d_in[6];   // [128] f32
    const float* Wnei  = (const float*)d_in[7];   // [128,128] f32
    const float* bnei  = (const float*)d_in[8];   // [128] f32
    float* out = (float*)d_out;

    const int E = in_sizes[4];
    const int num_tiles = (E + TILE_M - 1) / TILE_M;

    prep_w_kernel<<<32, 256>>>(Wself, Wnei, (const unsigned*)dme, E);

    int sm_count = 148;
    cudaDeviceGetAttribute(&sm_count, cudaDevAttrMultiProcessorCount, 0);
    int grid = 2 * sm_count;
    if (grid > num_tiles) grid = num_tiles;

    cudaFuncSetAttribute(fused_tsage_kernel,
                         cudaFuncAttributeMaxDynamicSharedMemorySize, SMEM_TOTAL);
    fused_tsage_kernel<<<grid, NTHREADS, SMEM_TOTAL>>>(
        src, dstf, dme, deg, bself, bnei, out, E, num_tiles);
}

// round 5
// speedup vs baseline: 1.6031x; 1.3719x over previous
#include <cuda_runtime.h>
#include <cuda_fp16.h>
#include <cstdint>

// ============================================================================
// FastTSAGEConv fused kernel for GB300 (plain sm_103 PTX feature set):
// legacy HMMA mma.sync.m16n8k16 fp16 (fp32 accum), 1-pass.
//
//   hn[e]  = (sum_{j=ss..me} src_feat[j]) / (deg[e]+1),  ss = me - deg + 1
//   out[e] = [dst_feat[e] | hn[e]] @ [W_self; W_neigh] + (b_self + b_neigh)
//
// R4 -> R5: latency-bound profile (all units < 36%) => raise occupancy to 3
// CTAs/SM by moving the B-fragment table from smem to L1-resident __ldg
// (smem/CTA 100KB -> 35KB), cap regs via __launch_bounds__(256,3), and
// unroll the segment-sum loop x4 with dual accumulators (MLP 2 -> 4).
// ============================================================================

#define TILE_M     64
#define NTHREADS   256
#define OCC        3

// ---- smem layout: only the A/stage region now ----
static constexpr int A_STRIDE_B = 528;          // bytes per A row (256 fp16 + 8 pad)
static constexpr int STG_STRIDE = 136;          // floats per out-stage row (pad 8)
// A fp16 [64][528B] = 33792 B ; out stage fp32 [64][136] = 34816 B (aliased)
static constexpr int SMEM_TOTAL = TILE_M * STG_STRIDE * 4;   // 34816

// Pre-packed B fragments: [kstep 0..15][nblock 0..15][lane 0..31] x 2 u32
// (64 KB, stays hot in L1 across the whole kernel)
__device__ uint2 g_bfrag[16 * 16 * 32];
// dtype flag for dst_max_eid: 1 if int64, 0 if int32
__device__ int g_eid_is64;

// ============================ helpers ===================================
__device__ __forceinline__ uint32_t smem_to_u32(const void* smem_ptr) {
    uint32_t addr;
    asm("{ .reg .u64 tmp; cvta.to.shared.u64 tmp, %1; cvt.u32.u64 %0, tmp; }"
        : "=r"(addr) : "l"(smem_ptr));
    return addr;
}

__device__ __forceinline__ uint32_t f22u(float a, float b) {
    __half2 h = __floats2half2_rn(a, b);
    return *reinterpret_cast<uint32_t*>(&h);
}

__device__ __forceinline__ void mma16816(float* c, const uint32_t* a,
                                         uint32_t b0, uint32_t b1) {
    asm volatile(
        "mma.sync.aligned.m16n8k16.row.col.f32.f16.f16.f32 "
        "{%0,%1,%2,%3}, {%4,%5,%6,%7}, {%8,%9}, {%0,%1,%2,%3};\n"
        : "+f"(c[0]), "+f"(c[1]), "+f"(c[2]), "+f"(c[3])
        : "r"(a[0]), "r"(a[1]), "r"(a[2]), "r"(a[3]), "r"(b0), "r"(b1));
}

// ============================================================================
// Prep kernel (also hosts the dtype probe in block 0): pack
// B = [W_self; W_neigh] (256 x 128 f32) into fp16 MMA fragment layout.
// For kstep s (k0=16s), nblock nb (n0=8nb), lane l:
//   kA = 16s + (l%4)*2,  n = 8nb + l/4
//   reg0 = half2( B[kA][n],   B[kA+1][n] )
//   reg1 = half2( B[kA+8][n], B[kA+9][n] )
// Probe: view dst_max_eid as int64 at elements [E/4, E/4+256) (word indices
// < E under either dtype). True int64 (values in [0,E)) => all high words 0;
// int32 data there holds values ~E/2 != 0.
// ============================================================================
__global__ void prep_w_kernel(const float* __restrict__ Wself,
                              const float* __restrict__ Wneigh,
                              const unsigned* __restrict__ dme_words, int E) {
    if (blockIdx.x == 0) {
        __shared__ int nz;
        if (threadIdx.x == 0) nz = 0;
        __syncthreads();
        int i = E / 4 + threadIdx.x;
        unsigned hi = dme_words[2 * i + 1];
        if (hi != 0u) atomicAdd(&nz, 1);
        __syncthreads();
        if (threadIdx.x == 0) g_eid_is64 = (nz == 0) ? 1 : 0;
    }
    int idx = blockIdx.x * blockDim.x + threadIdx.x;    // 0..8191
    if (idx >= 16 * 16 * 32) return;
    int lane = idx & 31;
    int nb   = (idx >> 5) & 15;
    int s    = idx >> 9;
    int k0 = s * 16 + (lane & 3) * 2;
    int n  = nb * 8 + (lane >> 2);

    auto wc = [&](int k) -> float {
        return (k < 128) ? Wself[k * 128 + n] : Wneigh[(k - 128) * 128 + n];
    };
    uint2 v;
    v.x = f22u(wc(k0),     wc(k0 + 1));
    v.y = f22u(wc(k0 + 8), wc(k0 + 9));
    g_bfrag[idx] = v;
}

// ============================================================================
// Main persistent kernel — 3 CTAs/SM
// ============================================================================
__global__ void __launch_bounds__(NTHREADS, OCC)
fused_tsage_kernel(const float* __restrict__ src_feat,
                   const float* __restrict__ dst_feat,
                   const int*   __restrict__ dst_max_eid,
                   const float* __restrict__ dst_deg,
                   const float* __restrict__ b_self,
                   const float* __restrict__ b_neigh,
                   float* __restrict__ out,
                   int E, int num_tiles) {
    extern __shared__ char smem[];
    const uint32_t smem_base = smem_to_u32(smem);
    const int tid = threadIdx.x;
    const int wid = tid >> 5;
    const int lid = tid & 31;
    const int wm  = wid & 3;        // M-warp 0..3  (rows wm*16 .. +15)
    const int wn  = wid >> 2;       // N-warp 0..1  (cols wn*64 .. +63)
    const int is64 = g_eid_is64;
    const long long* dme64 = reinterpret_cast<const long long*>(dst_max_eid);

    // per-lane bias for the coalesced epilogue (cols 4*lid..4*lid+3)
    const float bia0 = b_self[4 * lid + 0] + b_neigh[4 * lid + 0];
    const float bia1 = b_self[4 * lid + 1] + b_neigh[4 * lid + 1];
    const float bia2 = b_self[4 * lid + 2] + b_neigh[4 * lid + 2];
    const float bia3 = b_self[4 * lid + 3] + b_neigh[4 * lid + 3];

    // ldmatrix per-lane address pieces (A tile, 528B row stride)
    const int ldsm_row = (lid & 7) + ((lid >> 3) & 1) * 8;   // row within 16
    const int ldsm_k16 = (lid >> 4) * 16;                    // +16B for k 8..15
    const uint32_t a_base = smem_base;

    float* stage = reinterpret_cast<float*>(smem);           // fp32 view (aliased)
    // per-warp B fragment pointer (this warp's wn half), L1-resident
    const uint2* __restrict__ bfrag_w = g_bfrag + (size_t)(wn * 8) * 32 + lid;

    for (int t = blockIdx.x; t < num_tiles; t += gridDim.x) {
        const int m0 = t * TILE_M;

        // ========= producer phase: build A tile (fp16) ======================
        // dst_feat -> cols 0..127 ; hn -> cols 128..255 (warp-per-edge)
#pragma unroll 1
        for (int rr = 0; rr < 8; rr++) {
            const int r = wid * 8 + rr;
            const int e = m0 + r;
            if (e < E) {
                // issue dst load first so it overlaps the segsum chain
                float4 dv = __ldg(reinterpret_cast<const float4*>(
                    dst_feat + (size_t)e * 128 + 4 * lid));

                int me = is64 ? (int)dme64[e] : dst_max_eid[e];
                const float degf = dst_deg[e];
                if (me >= E) me = E - 1;           // bounded under any mis-parse
                if (me < 0)  me = 0;
                int ss = me - (int)degf + 1;
                if (ss < 0) ss = 0;

                // dual-accumulator segsum, unrolled x4 (MLP ~4)
                float ax = 0.f, ay = 0.f, az = 0.f, aw = 0.f;
                float bx = 0.f, by = 0.f, bz = 0.f, bw = 0.f;
                const float4* sp4 = reinterpret_cast<const float4*>(
                    src_feat + (size_t)ss * 128 + 4 * lid);
                const int cnt = me - ss + 1;
                int j = 0;
#pragma unroll 1
                for (; j + 4 <= cnt; j += 4) {
                    float4 v0 = __ldg(sp4 + (size_t)(j + 0) * 32);
                    float4 v1 = __ldg(sp4 + (size_t)(j + 1) * 32);
                    float4 v2 = __ldg(sp4 + (size_t)(j + 2) * 32);
                    float4 v3 = __ldg(sp4 + (size_t)(j + 3) * 32);
                    ax += v0.x; ay += v0.y; az += v0.z; aw += v0.w;
                    bx += v1.x; by += v1.y; bz += v1.z; bw += v1.w;
                    ax += v2.x; ay += v2.y; az += v2.z; aw += v2.w;
                    bx += v3.x; by += v3.y; bz += v3.z; bw += v3.w;
                }
#pragma unroll 1
                for (; j < cnt; j++) {
                    float4 v0 = __ldg(sp4 + (size_t)j * 32);
                    ax += v0.x; ay += v0.y; az += v0.z; aw += v0.w;
                }
                ax += bx; ay += by; az += bz; aw += bw;
                const float inv = 1.0f / (degf + 1.0f);

                uint32_t addr = a_base + (uint32_t)r * A_STRIDE_B + 8u * lid;
                uint32_t d01 = f22u(dv.x, dv.y);
                uint32_t d23 = f22u(dv.z, dv.w);
                asm volatile("st.shared.v2.b32 [%0], {%1,%2};"
                             :: "r"(addr), "r"(d01), "r"(d23) : "memory");
                uint32_t h01 = f22u(ax * inv, ay * inv);
                uint32_t h23 = f22u(az * inv, aw * inv);
                asm volatile("st.shared.v2.b32 [%0], {%1,%2};"
                             :: "r"(addr + 256u), "r"(h01), "r"(h23) : "memory");
            }
        }
        __syncthreads();

        // ========= MMA phase: warp tile 16x64, K=256 ========================
        float acc[8][4];
#pragma unroll
        for (int nb = 0; nb < 8; nb++)
#pragma unroll
            for (int q = 0; q < 4; q++) acc[nb][q] = 0.f;

#pragma unroll 4
        for (int s = 0; s < 16; s++) {
            uint32_t a[4];
            {
                const int row0 = wm * 16;
                uint32_t addr = a_base + (uint32_t)(row0 + ldsm_row) * A_STRIDE_B
                              + (uint32_t)ldsm_k16 + (uint32_t)s * 32u;
                asm volatile(
                    "ldmatrix.sync.aligned.m8n8.x4.shared.b16 {%0,%1,%2,%3}, [%4];"
                    : "=r"(a[0]), "=r"(a[1]), "=r"(a[2]), "=r"(a[3])
                    : "r"(addr));
            }
            const uint2* bp = bfrag_w + (size_t)(s * 16) * 32;
#pragma unroll
            for (int nb = 0; nb < 8; nb++) {
                uint2 b = __ldg(bp + (size_t)nb * 32);
                mma16816(acc[nb], a, b.x, b.y);
            }
        }
        __syncthreads();   // all warps done reading A before stage overwrite

        // ========= epilogue: regs -> fp32 stage (aliases A) =================
#pragma unroll
        for (int nb = 0; nb < 8; nb++) {
            const int r0 = wm * 16 + (lid >> 2);
            const int n  = wn * 64 + nb * 8 + (lid & 3) * 2;
            float* p0 = stage + r0 * STG_STRIDE + n;
            p0[0] = acc[nb][0];
            p0[1] = acc[nb][1];
            float* p1 = stage + (r0 + 8) * STG_STRIDE + n;
            p1[0] = acc[nb][2];
            p1[1] = acc[nb][3];
        }
        __syncthreads();

        // ========= coalesced store with bias ================================
#pragma unroll 2
        for (int rr = 0; rr < 8; rr++) {
            const int r = wid * 8 + rr;
            const int e = m0 + r;
            if (e < E) {
                const float* sp = stage + r * STG_STRIDE + 4 * lid;
                float4 v;
                v.x = sp[0] + bia0;
                v.y = sp[1] + bia1;
                v.z = sp[2] + bia2;
                v.w = sp[3] + bia3;
                *reinterpret_cast<float4*>(out + (size_t)e * 128 + 4 * lid) = v;
            }
        }
        __syncthreads();   // stage free before next tile's A writes
    }
}

// ============================================================================
// Launch
// ============================================================================
extern "C" void kernel_launch(void* const* d_in, const int* in_sizes, int n_in,
                              void* d_out, int out_size) {
    const float* src   = (const float*)d_in[0];   // src_feat   [E,128] f32
    const float* dstf  = (const float*)d_in[1];   // dst_feat   [E,128] f32
    // d_in[2] = dst_ids (unused: seg_start = dst_max_eid - deg + 1)
    const int*   dme   = (const int*)  d_in[3];   // dst_max_eid [E] i32 or i64
    const float* deg   = (const float*)d_in[4];   // dst_deg    [E] f32
    const float* Wself = (const float*)d_in[5];   // [128,128] f32
    const float* bself = (const float*)d_in[6];   // [128] f32
    const float* Wnei  = (const float*)d_in[7];   // [128,128] f32
    const float* bnei  = (const float*)d_in[8];   // [128] f32
    float* out = (float*)d_out;

    const int E = in_sizes[4];
    const int num_tiles = (E + TILE_M - 1) / TILE_M;

    prep_w_kernel<<<32, 256>>>(Wself, Wnei, (const unsigned*)dme, E);

    int sm_count = 148;
    cudaDeviceGetAttribute(&sm_count, cudaDevAttrMultiProcessorCount, 0);
    int grid = OCC * sm_count;
    if (grid > num_tiles) grid = num_tiles;

    cudaFuncSetAttribute(fused_tsage_kernel,
                         cudaFuncAttributeMaxDynamicSharedMemorySize, SMEM_TOTAL);
    fused_tsage_kernel<<<grid, NTHREADS, SMEM_TOTAL>>>(
        src, dstf, dme, deg, bself, bnei, out, E, num_tiles);
}

// round 6
// speedup vs baseline: 1.7263x; 1.0769x over previous
#include <cuda_runtime.h>
#include <cuda_fp16.h>
#include <cstdint>

// ============================================================================
// FastTSAGEConv fused kernel for GB300 (plain sm_103 PTX feature set):
// legacy HMMA mma.sync.m16n8k16 fp16 (fp32 accum), 1-pass.
//
//   hn[e]  = (sum_{j=ss..me} src_feat[j]) / (deg[e]+1),  ss = me - deg + 1
//   out[e] = [dst_feat[e] | hn[e]] @ [W_self; W_neigh] + (b_self + b_neigh)
//
// R5 -> R6: occupancy 3 -> 4 CTAs/SM (launch_bounds reg cap 80 -> 64).
// Latency-bound scaling has been ~linear in resident warps for two rounds;
// regs are the binding resource (smem 4x34.8KB=139KB fits, L1D 89KB left
// covers the 64KB L1-resident B-fragment table).
// ============================================================================

#define TILE_M     64
#define NTHREADS   256
#define OCC        4

// ---- smem layout: only the A/stage region ----
static constexpr int A_STRIDE_B = 528;          // bytes per A row (256 fp16 + 8 pad)
static constexpr int STG_STRIDE = 136;          // floats per out-stage row (pad 8)
// A fp16 [64][528B] = 33792 B ; out stage fp32 [64][136] = 34816 B (aliased)
static constexpr int SMEM_TOTAL = TILE_M * STG_STRIDE * 4;   // 34816

// Pre-packed B fragments: [kstep 0..15][nblock 0..15][lane 0..31] x 2 u32
// (64 KB, stays hot in L1 across the whole kernel)
__device__ uint2 g_bfrag[16 * 16 * 32];
// dtype flag for dst_max_eid: 1 if int64, 0 if int32
__device__ int g_eid_is64;

// ============================ helpers ===================================
__device__ __forceinline__ uint32_t smem_to_u32(const void* smem_ptr) {
    uint32_t addr;
    asm("{ .reg .u64 tmp; cvta.to.shared.u64 tmp, %1; cvt.u32.u64 %0, tmp; }"
        : "=r"(addr) : "l"(smem_ptr));
    return addr;
}

__device__ __forceinline__ uint32_t f22u(float a, float b) {
    __half2 h = __floats2half2_rn(a, b);
    return *reinterpret_cast<uint32_t*>(&h);
}

__device__ __forceinline__ void mma16816(float* c, const uint32_t* a,
                                         uint32_t b0, uint32_t b1) {
    asm volatile(
        "mma.sync.aligned.m16n8k16.row.col.f32.f16.f16.f32 "
        "{%0,%1,%2,%3}, {%4,%5,%6,%7}, {%8,%9}, {%0,%1,%2,%3};\n"
        : "+f"(c[0]), "+f"(c[1]), "+f"(c[2]), "+f"(c[3])
        : "r"(a[0]), "r"(a[1]), "r"(a[2]), "r"(a[3]), "r"(b0), "r"(b1));
}

// ============================================================================
// Prep kernel (also hosts the dtype probe in block 0): pack
// B = [W_self; W_neigh] (256 x 128 f32) into fp16 MMA fragment layout.
// For kstep s (k0=16s), nblock nb (n0=8nb), lane l:
//   kA = 16s + (l%4)*2,  n = 8nb + l/4
//   reg0 = half2( B[kA][n],   B[kA+1][n] )
//   reg1 = half2( B[kA+8][n], B[kA+9][n] )
// Probe: view dst_max_eid as int64 at elements [E/4, E/4+256) (word indices
// < E under either dtype). True int64 (values in [0,E)) => all high words 0;
// int32 data there holds values ~E/2 != 0.
// ============================================================================
__global__ void prep_w_kernel(const float* __restrict__ Wself,
                              const float* __restrict__ Wneigh,
                              const unsigned* __restrict__ dme_words, int E) {
    if (blockIdx.x == 0) {
        __shared__ int nz;
        if (threadIdx.x == 0) nz = 0;
        __syncthreads();
        int i = E / 4 + threadIdx.x;
        unsigned hi = dme_words[2 * i + 1];
        if (hi != 0u) atomicAdd(&nz, 1);
        __syncthreads();
        if (threadIdx.x == 0) g_eid_is64 = (nz == 0) ? 1 : 0;
    }
    int idx = blockIdx.x * blockDim.x + threadIdx.x;    // 0..8191
    if (idx >= 16 * 16 * 32) return;
    int lane = idx & 31;
    int nb   = (idx >> 5) & 15;
    int s    = idx >> 9;
    int k0 = s * 16 + (lane & 3) * 2;
    int n  = nb * 8 + (lane >> 2);

    auto wc = [&](int k) -> float {
        return (k < 128) ? Wself[k * 128 + n] : Wneigh[(k - 128) * 128 + n];
    };
    uint2 v;
    v.x = f22u(wc(k0),     wc(k0 + 1));
    v.y = f22u(wc(k0 + 8), wc(k0 + 9));
    g_bfrag[idx] = v;
}

// ============================================================================
// Main persistent kernel — 4 CTAs/SM
// ============================================================================
__global__ void __launch_bounds__(NTHREADS, OCC)
fused_tsage_kernel(const float* __restrict__ src_feat,
                   const float* __restrict__ dst_feat,
                   const int*   __restrict__ dst_max_eid,
                   const float* __restrict__ dst_deg,
                   const float* __restrict__ b_self,
                   const float* __restrict__ b_neigh,
                   float* __restrict__ out,
                   int E, int num_tiles) {
    extern __shared__ char smem[];
    const uint32_t smem_base = smem_to_u32(smem);
    const int tid = threadIdx.x;
    const int wid = tid >> 5;
    const int lid = tid & 31;
    const int wm  = wid & 3;        // M-warp 0..3  (rows wm*16 .. +15)
    const int wn  = wid >> 2;       // N-warp 0..1  (cols wn*64 .. +63)
    const int is64 = g_eid_is64;
    const long long* dme64 = reinterpret_cast<const long long*>(dst_max_eid);

    // per-lane bias for the coalesced epilogue (cols 4*lid..4*lid+3)
    const float bia0 = b_self[4 * lid + 0] + b_neigh[4 * lid + 0];
    const float bia1 = b_self[4 * lid + 1] + b_neigh[4 * lid + 1];
    const float bia2 = b_self[4 * lid + 2] + b_neigh[4 * lid + 2];
    const float bia3 = b_self[4 * lid + 3] + b_neigh[4 * lid + 3];

    // ldmatrix per-lane address pieces (A tile, 528B row stride)
    const int ldsm_row = (lid & 7) + ((lid >> 3) & 1) * 8;   // row within 16
    const int ldsm_k16 = (lid >> 4) * 16;                    // +16B for k 8..15
    const uint32_t a_base = smem_base;

    float* stage = reinterpret_cast<float*>(smem);           // fp32 view (aliased)
    // per-warp B fragment pointer (this warp's wn half), L1-resident
    const uint2* __restrict__ bfrag_w = g_bfrag + (size_t)(wn * 8) * 32 + lid;

    for (int t = blockIdx.x; t < num_tiles; t += gridDim.x) {
        const int m0 = t * TILE_M;

        // ========= producer phase: build A tile (fp16) ======================
        // dst_feat -> cols 0..127 ; hn -> cols 128..255 (warp-per-edge)
#pragma unroll 1
        for (int rr = 0; rr < 8; rr++) {
            const int r = wid * 8 + rr;
            const int e = m0 + r;
            if (e < E) {
                // issue dst load first so it overlaps the segsum chain
                float4 dv = __ldg(reinterpret_cast<const float4*>(
                    dst_feat + (size_t)e * 128 + 4 * lid));

                int me = is64 ? (int)dme64[e] : dst_max_eid[e];
                const float degf = dst_deg[e];
                if (me >= E) me = E - 1;           // bounded under any mis-parse
                if (me < 0)  me = 0;
                int ss = me - (int)degf + 1;
                if (ss < 0) ss = 0;

                // dual-accumulator segsum, unrolled x4 (MLP ~4)
                float ax = 0.f, ay = 0.f, az = 0.f, aw = 0.f;
                float bx = 0.f, by = 0.f, bz = 0.f, bw = 0.f;
                const float4* sp4 = reinterpret_cast<const float4*>(
                    src_feat + (size_t)ss * 128 + 4 * lid);
                const int cnt = me - ss + 1;
                int j = 0;
#pragma unroll 1
                for (; j + 4 <= cnt; j += 4) {
                    float4 v0 = __ldg(sp4 + (size_t)(j + 0) * 32);
                    float4 v1 = __ldg(sp4 + (size_t)(j + 1) * 32);
                    float4 v2 = __ldg(sp4 + (size_t)(j + 2) * 32);
                    float4 v3 = __ldg(sp4 + (size_t)(j + 3) * 32);
                    ax += v0.x; ay += v0.y; az += v0.z; aw += v0.w;
                    bx += v1.x; by += v1.y; bz += v1.z; bw += v1.w;
                    ax += v2.x; ay += v2.y; az += v2.z; aw += v2.w;
                    bx += v3.x; by += v3.y; bz += v3.z; bw += v3.w;
                }
#pragma unroll 1
                for (; j < cnt; j++) {
                    float4 v0 = __ldg(sp4 + (size_t)j * 32);
                    ax += v0.x; ay += v0.y; az += v0.z; aw += v0.w;
                }
                ax += bx; ay += by; az += bz; aw += bw;
                const float inv = 1.0f / (degf + 1.0f);

                uint32_t addr = a_base + (uint32_t)r * A_STRIDE_B + 8u * lid;
                uint32_t d01 = f22u(dv.x, dv.y);
                uint32_t d23 = f22u(dv.z, dv.w);
                asm volatile("st.shared.v2.b32 [%0], {%1,%2};"
                             :: "r"(addr), "r"(d01), "r"(d23) : "memory");
                uint32_t h01 = f22u(ax * inv, ay * inv);
                uint32_t h23 = f22u(az * inv, aw * inv);
                asm volatile("st.shared.v2.b32 [%0], {%1,%2};"
                             :: "r"(addr + 256u), "r"(h01), "r"(h23) : "memory");
            }
        }
        __syncthreads();

        // ========= MMA phase: warp tile 16x64, K=256 ========================
        float acc[8][4];
#pragma unroll
        for (int nb = 0; nb < 8; nb++)
#pragma unroll
            for (int q = 0; q < 4; q++) acc[nb][q] = 0.f;

#pragma unroll 4
        for (int s = 0; s < 16; s++) {
            uint32_t a[4];
            {
                const int row0 = wm * 16;
                uint32_t addr = a_base + (uint32_t)(row0 + ldsm_row) * A_STRIDE_B
                              + (uint32_t)ldsm_k16 + (uint32_t)s * 32u;
                asm volatile(
                    "ldmatrix.sync.aligned.m8n8.x4.shared.b16 {%0,%1,%2,%3}, [%4];"
                    : "=r"(a[0]), "=r"(a[1]), "=r"(a[2]), "=r"(a[3])
                    : "r"(addr));
            }
            const uint2* bp = bfrag_w + (size_t)(s * 16) * 32;
#pragma unroll
            for (int nb = 0; nb < 8; nb++) {
                uint2 b = __ldg(bp + (size_t)nb * 32);
                mma16816(acc[nb], a, b.x, b.y);
            }
        }
        __syncthreads();   // all warps done reading A before stage overwrite

        // ========= epilogue: regs -> fp32 stage (aliases A) =================
#pragma unroll
        for (int nb = 0; nb < 8; nb++) {
            const int r0 = wm * 16 + (lid >> 2);
            const int n  = wn * 64 + nb * 8 + (lid & 3) * 2;
            float* p0 = stage + r0 * STG_STRIDE + n;
            p0[0] = acc[nb][0];
            p0[1] = acc[nb][1];
            float* p1 = stage + (r0 + 8) * STG_STRIDE + n;
            p1[0] = acc[nb][2];
            p1[1] = acc[nb][3];
        }
        __syncthreads();

        // ========= coalesced store with bias ================================
#pragma unroll 2
        for (int rr = 0; rr < 8; rr++) {
            const int r = wid * 8 + rr;
            const int e = m0 + r;
            if (e < E) {
                const float* sp = stage + r * STG_STRIDE + 4 * lid;
                float4 v;
                v.x = sp[0] + bia0;
                v.y = sp[1] + bia1;
                v.z = sp[2] + bia2;
                v.w = sp[3] + bia3;
                *reinterpret_cast<float4*>(out + (size_t)e * 128 + 4 * lid) = v;
            }
        }
        __syncthreads();   // stage free before next tile's A writes
    }
}

// ============================================================================
// Launch
// ============================================================================
extern "C" void kernel_launch(void* const* d_in, const int* in_sizes, int n_in,
                              void* d_out, int out_size) {
    const float* src   = (const float*)d_in[0];   // src_feat   [E,128] f32
    const float* dstf  = (const float*)d_in[1];   // dst_feat   [E,128] f32
    // d_in[2] = dst_ids (unused: seg_start = dst_max_eid - deg + 1)
    const int*   dme   = (const int*)  d_in[3];   // dst_max_eid [E] i32 or i64
    const float* deg   = (const float*)d_in[4];   // dst_deg    [E] f32
    const float* Wself = (const float*)d_in[5];   // [128,128] f32
    const float* bself = (const float*)d_in[6];   // [128] f32
    const float* Wnei  = (const float*)d_in[7];   // [128,128] f32
    const float* bnei  = (const float*)d_in[8];   // [128] f32
    float* out = (float*)d_out;

    const int E = in_sizes[4];
    const int num_tiles = (E + TILE_M - 1) / TILE_M;

    prep_w_kernel<<<32, 256>>>(Wself, Wnei, (const unsigned*)dme, E);

    int sm_count = 148;
    cudaDeviceGetAttribute(&sm_count, cudaDevAttrMultiProcessorCount, 0);
    int grid = OCC * sm_count;
    if (grid > num_tiles) grid = num_tiles;

    cudaFuncSetAttribute(fused_tsage_kernel,
                         cudaFuncAttributeMaxDynamicSharedMemorySize, SMEM_TOTAL);
    fused_tsage_kernel<<<grid, NTHREADS, SMEM_TOTAL>>>(
        src, dstf, dme, deg, bself, bnei, out, E, num_tiles);
}